// round 17
// baseline (speedup 1.0000x reference)
// build-id: r17-async-hgemm
#include <cuda_runtime.h>
#include <cuda_fp16.h>
#include <math.h>
#include <stdint.h>
#include <string.h>

// Problem constants
#define DIMC   1024
#define HEADS  16
#define HDIM   64
#define BATCH  2
#define SEQ    2048
#define ROWS   (BATCH*SEQ)          // 4096
#define QKVC   (3*DIMC)             // 3072

// ---------------- scratch (static device memory; no cudaMalloc allowed) ----
__device__ float  g_qkv  [ROWS * QKVC];            // x @ Wqkv (fp32)
__device__ float  g_q    [BATCH*HEADS*SEQ*HDIM];   // [B,H,N,HD] rope'd+scaled
__device__ float  g_k    [BATCH*HEADS*SEQ*HDIM];
__device__ float  g_v    [BATCH*HEADS*SEQ*HDIM];
__device__ __half g_xh   [ROWS * DIMC];            // fp16 copies of GEMM inputs
__device__ __half g_wqkvh[DIMC * QKVC];
__device__ __half g_wph  [DIMC * DIMC];
__device__ __half g_attnh[ROWS * DIMC];            // attention out, fp16 [B,N,DIM]

// ============================================================================
// helpers
// ============================================================================
__device__ __forceinline__ uint32_t packh2(float lo, float hi) {
    __half2 h = __float22half2_rn(make_float2(lo, hi));  // .x -> low 16 bits
    uint32_t u;
    memcpy(&u, &h, 4);
    return u;
}

__device__ __forceinline__ void mma_f16(float d[4], const uint32_t a[4],
                                        const uint32_t b[2]) {
    asm volatile(
        "mma.sync.aligned.m16n8k16.row.col.f32.f16.f16.f32 "
        "{%0,%1,%2,%3}, {%4,%5,%6,%7}, {%8,%9}, {%0,%1,%2,%3};"
        : "+f"(d[0]), "+f"(d[1]), "+f"(d[2]), "+f"(d[3])
        : "r"(a[0]), "r"(a[1]), "r"(a[2]), "r"(a[3]), "r"(b[0]), "r"(b[1]));
}

__device__ __forceinline__ void cp16(uint32_t smem_dst, const void* gsrc) {
    asm volatile("cp.async.cg.shared.global [%0], [%1], 16;"
                 :: "r"(smem_dst), "l"(gsrc));
}
__device__ __forceinline__ void cp_commit() {
    asm volatile("cp.async.commit_group;");
}
__device__ __forceinline__ void cp_wait2() {
    asm volatile("cp.async.wait_group 2;");
}

__device__ __forceinline__ void ldsm_x4(uint32_t r[4], uint32_t a) {
    asm volatile("ldmatrix.sync.aligned.m8n8.x4.shared.b16 {%0,%1,%2,%3}, [%4];"
                 : "=r"(r[0]), "=r"(r[1]), "=r"(r[2]), "=r"(r[3]) : "r"(a));
}
__device__ __forceinline__ void ldsm_x2t(uint32_t r[2], uint32_t a) {
    asm volatile("ldmatrix.sync.aligned.m8n8.x2.trans.shared.b16 {%0,%1}, [%2];"
                 : "=r"(r[0]), "=r"(r[1]) : "r"(a));
}

// ============================================================================
// Kernel 0: fp32 -> fp16 bulk convert (round-to-nearest, same as in-GEMM cvt)
// ============================================================================
__global__ __launch_bounds__(256)
void f2h_kernel(const float* __restrict__ s, __half* __restrict__ d, int n)
{
    int i = (blockIdx.x * 256 + threadIdx.x) * 8;
    if (i >= n) return;
    float4 a = *(const float4*)(s + i);
    float4 b = *(const float4*)(s + i + 4);
    uint4 w;
    w.x = packh2(a.x, a.y); w.y = packh2(a.z, a.w);
    w.z = packh2(b.x, b.y); w.w = packh2(b.z, b.w);
    *(uint4*)(d + i) = w;
}

// ============================================================================
// Kernel 1/4: fp16 async GEMM  C[M,N](fp32) = A[M,K](fp16) @ B[K,N](fp16) +bias
// 128x128x16 tile, 8 warps (2m x 4n), warp tile 64x32.
// 4-stage cp.async pipeline (window ~3 compute sections), ldmatrix fragments.
// As[m][k]: 24-half rows (12-word stride: ldmatrix rows {12r mod 32} distinct
// -> conflict-free). Bs[k][n]: 136-half rows ({4k} distinct -> conflict-free),
// B fragments via ldmatrix.x2.trans. All dims multiples of tiles; no guards.
// ============================================================================
#define STG 4
#define AST 24      // As row stride, halves
#define BST 136     // Bs row stride, halves

__global__ __launch_bounds__(256, 2)
void hgemm_async_kernel(const __half* __restrict__ A, const __half* __restrict__ B,
                        float* __restrict__ C, int M, int N, int K,
                        const float* __restrict__ bias)
{
    __shared__ __align__(16) __half As[STG][128 * AST];   // 24.0 KB
    __shared__ __align__(16) __half Bs[STG][16 * BST];    // 17.0 KB

    int tid  = threadIdx.x;
    int warp = tid >> 5, lane = tid & 31;
    int g  = lane >> 2;
    int tg = lane & 3;
    int wm = (warp >> 2) * 64;
    int wn = (warp & 3) * 32;

    int brow = blockIdx.y * 128;
    int bcol = blockIdx.x * 128;

    // cp.async per-thread coords: A: 128 rows x 2 16B-chunks; B: 16 k-rows x 16 chunks
    int ar = tid & 127, ac = (tid >> 7) * 8;       // row, half-offset in k
    int bk = tid >> 4,  bn = (tid & 15) * 8;       // k-row, half-offset in n
    const __half* Ag = A + (size_t)(brow + ar) * K + ac;
    const __half* Bg = B + (size_t)bk * N + bcol + bn;
    uint32_t As_s[STG], Bs_s[STG];
    #pragma unroll
    for (int s = 0; s < STG; s++) {
        As_s[s] = (uint32_t)__cvta_generic_to_shared(&As[s][ar * AST + ac]);
        Bs_s[s] = (uint32_t)__cvta_generic_to_shared(&Bs[s][bk * BST + bn]);
    }

    const int NT = K / 16;

    // prologue: stages 0..2
    #pragma unroll
    for (int s = 0; s < STG - 1; s++) {
        cp16(As_s[s], Ag + s * 16);
        cp16(Bs_s[s], Bg + (size_t)(s * 16) * N);
        cp_commit();
    }

    float d[4][4][4];
    #pragma unroll
    for (int mi = 0; mi < 4; mi++)
        #pragma unroll
        for (int ni = 0; ni < 4; ni++)
            #pragma unroll
            for (int r = 0; r < 4; r++) d[mi][ni][r] = 0.f;

    int j = lane >> 3, r8 = lane & 7;
    int krow = ((lane >> 3) & 1) * 8 + (lane & 7);     // B ldmatrix row (lanes 0-15 live)

    for (int t = 0; t < NT; t++) {
        cp_wait2();           // group t complete (<=2 pending)
        __syncthreads();      // stage visible to all; prior reads of reused stage done

        int tn = t + STG - 1;
        if (tn < NT) {        // refill stage (t+3)&3
            int s = tn & 3;
            cp16(As_s[s], Ag + tn * 16);
            cp16(Bs_s[s], Bg + (size_t)(tn * 16) * N);
        }
        cp_commit();          // commit every iter (possibly empty) to keep count

        int s = t & 3;
        uint32_t af[4][4], bf[4][2];
        #pragma unroll
        for (int mi = 0; mi < 4; mi++) {
            int row = wm + mi * 16 + (j & 1) * 8 + r8;
            uint32_t a = (uint32_t)__cvta_generic_to_shared(
                &As[s][row * AST + (j >> 1) * 8]);
            ldsm_x4(af[mi], a);
        }
        #pragma unroll
        for (int ni = 0; ni < 4; ni++) {
            uint32_t a = (uint32_t)__cvta_generic_to_shared(
                &Bs[s][krow * BST + wn + ni * 8]);
            ldsm_x2t(bf[ni], a);
        }
        #pragma unroll
        for (int mi = 0; mi < 4; mi++)
            #pragma unroll
            for (int ni = 0; ni < 4; ni++)
                mma_f16(d[mi][ni], af[mi], bf[ni]);
        __syncthreads();      // reads done before this stage is refilled
    }

    // epilogue: c0=[g][2tg] c1=[g][2tg+1] c2=[g+8][2tg] c3=[g+8][2tg+1]
    #pragma unroll
    for (int mi = 0; mi < 4; mi++) {
        #pragma unroll
        for (int ni = 0; ni < 4; ni++) {
            int r0 = brow + wm + mi * 16 + g;
            int c  = bcol + wn + ni * 8 + 2 * tg;
            float2 v0, v1;
            v0.x = d[mi][ni][0]; v0.y = d[mi][ni][1];
            v1.x = d[mi][ni][2]; v1.y = d[mi][ni][3];
            if (bias) {
                float2 bb = *(const float2*)(bias + c);
                v0.x += bb.x; v0.y += bb.y;
                v1.x += bb.x; v1.y += bb.y;
            }
            *(float2*)(C + (size_t)r0 * N + c)       = v0;
            *(float2*)(C + (size_t)(r0 + 8) * N + c) = v1;
        }
    }
}

// ============================================================================
// Kernel 2: per-head LayerNorm + RoPE + scatter to [B,H,N,HD].  (unchanged)
// ============================================================================
__global__ __launch_bounds__(256)
void lnrope_kernel(const float* __restrict__ freq,
                   const float* __restrict__ qg, const float* __restrict__ qb,
                   const float* __restrict__ kg, const float* __restrict__ kb)
{
    int warp = (blockIdx.x * blockDim.x + threadIdx.x) >> 5;
    int lane = threadIdx.x & 31;
    const int TOTAL = BATCH * SEQ * HEADS;
    if (warp >= TOTAL) return;

    int h = warp & (HEADS - 1);
    int n = (warp >> 4) & (SEQ - 1);
    int b = warp >> 15;

    const float* src = g_qkv + (size_t)(b * SEQ + n) * QKVC + h * HDIM;
    int d0 = lane * 2;

    float2 q2 = *(const float2*)(src + d0);
    float2 k2 = *(const float2*)(src + DIMC + d0);
    float2 v2 = *(const float2*)(src + 2 * DIMC + d0);

    float sq  = q2.x + q2.y,           sk  = k2.x + k2.y;
    float sq2 = q2.x*q2.x + q2.y*q2.y, sk2 = k2.x*k2.x + k2.y*k2.y;
    #pragma unroll
    for (int off = 16; off; off >>= 1) {
        sq  += __shfl_xor_sync(0xffffffffu, sq,  off);
        sq2 += __shfl_xor_sync(0xffffffffu, sq2, off);
        sk  += __shfl_xor_sync(0xffffffffu, sk,  off);
        sk2 += __shfl_xor_sync(0xffffffffu, sk2, off);
    }
    float qm = sq * (1.f/64.f);
    float qv = sq2 * (1.f/64.f) - qm * qm;
    float qi = rsqrtf(qv + 1e-5f);
    float km = sk * (1.f/64.f);
    float kv = sk2 * (1.f/64.f) - km * km;
    float ki = rsqrtf(kv + 1e-5f);

    float qn0 = (q2.x - qm) * qi * qg[d0]     + qb[d0];
    float qn1 = (q2.y - qm) * qi * qg[d0 + 1] + qb[d0 + 1];
    float kn0 = (k2.x - km) * ki * kg[d0]     + kb[d0];
    float kn1 = (k2.y - km) * ki * kg[d0 + 1] + kb[d0 + 1];

    float co = freq[(n * 32 + lane) * 2 + 0];
    float si = freq[(n * 32 + lane) * 2 + 1];
    float qr = (qn0 * co - qn1 * si) * 0.125f;
    float qe = (qn0 * si + qn1 * co) * 0.125f;
    float kr =  kn0 * co - kn1 * si;
    float ke =  kn0 * si + kn1 * co;

    size_t o = ((size_t)(b * HEADS + h) * SEQ + n) * HDIM + d0;
    *(float2*)(g_q + o) = make_float2(qr, qe);
    *(float2*)(g_k + o) = make_float2(kr, ke);
    *(float2*)(g_v + o) = v2;
}

// ============================================================================
// Kernel 3: flash attention on fp16 tensor cores (R15 kernel, unchanged except
// the epilogue now writes fp16 directly — same __float2half_rn rounding the
// proj GEMM staging applied in R16, so proj numerics are bit-identical).
// ============================================================================
__global__ __launch_bounds__(256)
void attn_mma_kernel()
{
    __shared__ uint32_t Ks[64 * 36];    // h2 [key][d2]
    __shared__ uint32_t Vt[64 * 33];    // h2 [d][key2] (half stride 66)

    int qt  = blockIdx.x;               // 0..15
    int bh  = blockIdx.y;               // 0..31
    int tid = threadIdx.x;
    int warp = tid >> 5, lane = tid & 31;
    int g = lane >> 2, tg = lane & 3;

    const float* Qb = g_q + ((size_t)bh * SEQ + qt * 128 + warp * 16) * HDIM;
    const float* Kb = g_k + (size_t)bh * SEQ * HDIM;
    const float* Vb = g_v + (size_t)bh * SEQ * HDIM;

    // Q fragments (fp16): qf[ki] covers dims ki*16..ki*16+15
    uint32_t qf[4][4];
    #pragma unroll
    for (int ki = 0; ki < 4; ki++) {
        const float* q0 = Qb + g * HDIM + ki * 16;
        const float* q1 = Qb + (g + 8) * HDIM + ki * 16;
        float2 t;
        t = *(const float2*)(q0 + 2 * tg);     qf[ki][0] = packh2(t.x, t.y);
        t = *(const float2*)(q1 + 2 * tg);     qf[ki][1] = packh2(t.x, t.y);
        t = *(const float2*)(q0 + 2 * tg + 8); qf[ki][2] = packh2(t.x, t.y);
        t = *(const float2*)(q1 + 2 * tg + 8); qf[ki][3] = packh2(t.x, t.y);
    }

    float oc[8][4];
    #pragma unroll
    for (int ni = 0; ni < 8; ni++)
        #pragma unroll
        for (int r = 0; r < 4; r++) oc[ni][r] = 0.f;
    float m0 = -INFINITY, m1 = -INFINITY, l0 = 0.f, l1 = 0.f;

    float4 pk[4], pv[4];
    #pragma unroll
    for (int u = 0; u < 4; u++) {
        int i  = tid + u * 256;
        int r  = i >> 4;
        int d4 = (i & 15) * 4;
        pk[u] = *(const float4*)(Kb + (size_t)r * HDIM + d4);
        pv[u] = *(const float4*)(Vb + (size_t)r * HDIM + d4);
    }

    for (int kt = 0; kt < SEQ / 64; kt++) {
        #pragma unroll
        for (int u = 0; u < 4; u++) {
            int i  = tid + u * 256;
            int r  = i >> 4;
            int d4 = (i & 15) * 4;
            uint2 kw;
            kw.x = packh2(pk[u].x, pk[u].y);
            kw.y = packh2(pk[u].z, pk[u].w);
            *(uint2*)&Ks[r * 36 + (d4 >> 1)] = kw;
            __half* vh = (__half*)Vt;
            vh[(d4 + 0) * 66 + r] = __float2half_rn(pv[u].x);
            vh[(d4 + 1) * 66 + r] = __float2half_rn(pv[u].y);
            vh[(d4 + 2) * 66 + r] = __float2half_rn(pv[u].z);
            vh[(d4 + 3) * 66 + r] = __float2half_rn(pv[u].w);
        }
        __syncthreads();

        if (kt + 1 < SEQ / 64) {
            #pragma unroll
            for (int u = 0; u < 4; u++) {
                int i  = tid + u * 256;
                int r  = (kt + 1) * 64 + (i >> 4);
                int d4 = (i & 15) * 4;
                pk[u] = *(const float4*)(Kb + (size_t)r * HDIM + d4);
                pv[u] = *(const float4*)(Vb + (size_t)r * HDIM + d4);
            }
        }

        float sc[8][4];
        #pragma unroll
        for (int ni = 0; ni < 8; ni++)
            #pragma unroll
            for (int r = 0; r < 4; r++) sc[ni][r] = 0.f;
        #pragma unroll
        for (int ki = 0; ki < 4; ki++) {
            #pragma unroll
            for (int ni = 0; ni < 8; ni++) {
                uint32_t b[2];
                b[0] = Ks[(ni * 8 + g) * 36 + ki * 8 + tg    ];
                b[1] = Ks[(ni * 8 + g) * 36 + ki * 8 + tg + 4];
                mma_f16(sc[ni], qf[ki], b);
            }
        }

        float mx0 = -INFINITY, mx1 = -INFINITY;
        #pragma unroll
        for (int ni = 0; ni < 8; ni++) {
            mx0 = fmaxf(mx0, fmaxf(sc[ni][0], sc[ni][1]));
            mx1 = fmaxf(mx1, fmaxf(sc[ni][2], sc[ni][3]));
        }
        mx0 = fmaxf(mx0, __shfl_xor_sync(0xffffffffu, mx0, 1));
        mx0 = fmaxf(mx0, __shfl_xor_sync(0xffffffffu, mx0, 2));
        mx1 = fmaxf(mx1, __shfl_xor_sync(0xffffffffu, mx1, 1));
        mx1 = fmaxf(mx1, __shfl_xor_sync(0xffffffffu, mx1, 2));

        float mn0 = fmaxf(m0, mx0), mn1 = fmaxf(m1, mx1);
        float a0 = __expf(m0 - mn0), a1 = __expf(m1 - mn1);

        uint32_t pa[4][4];
        float s0 = 0.f, s1 = 0.f;
        #pragma unroll
        for (int ni = 0; ni < 8; ni++) {
            float p0 = __expf(sc[ni][0] - mn0);
            float p1 = __expf(sc[ni][1] - mn0);
            float p2 = __expf(sc[ni][2] - mn1);
            float p3 = __expf(sc[ni][3] - mn1);
            s0 += p0 + p1; s1 += p2 + p3;
            int ki = ni >> 1;
            if (ni & 1) { pa[ki][2] = packh2(p0, p1); pa[ki][3] = packh2(p2, p3); }
            else        { pa[ki][0] = packh2(p0, p1); pa[ki][1] = packh2(p2, p3); }
        }
        s0 += __shfl_xor_sync(0xffffffffu, s0, 1);
        s0 += __shfl_xor_sync(0xffffffffu, s0, 2);
        s1 += __shfl_xor_sync(0xffffffffu, s1, 1);
        s1 += __shfl_xor_sync(0xffffffffu, s1, 2);

        l0 = a0 * l0 + s0;  l1 = a1 * l1 + s1;
        m0 = mn0;           m1 = mn1;
        #pragma unroll
        for (int ni = 0; ni < 8; ni++) {
            oc[ni][0] *= a0; oc[ni][1] *= a0;
            oc[ni][2] *= a1; oc[ni][3] *= a1;
        }

        #pragma unroll
        for (int ki = 0; ki < 4; ki++) {
            #pragma unroll
            for (int ni = 0; ni < 8; ni++) {
                uint32_t b[2];
                b[0] = Vt[(ni * 8 + g) * 33 + ki * 8 + tg    ];
                b[1] = Vt[(ni * 8 + g) * 33 + ki * 8 + tg + 4];
                mma_f16(oc[ni], pa[ki], b);
            }
        }
        __syncthreads();
    }

    // epilogue: normalize, write fp16 [B, N, DIM] (rn rounding = R16's staging)
    int b = bh >> 4, h = bh & 15;
    int row0 = qt * 128 + warp * 16 + g;
    float i0 = 1.f / l0, i1 = 1.f / l1;
    uint32_t* outh = (uint32_t*)g_attnh;
    #pragma unroll
    for (int ni = 0; ni < 8; ni++) {
        int d = h * HDIM + ni * 8 + 2 * tg;   // even
        outh[(((size_t)(b * SEQ + row0    )) * DIMC + d) >> 1] =
            packh2(oc[ni][0] * i0, oc[ni][1] * i0);
        outh[(((size_t)(b * SEQ + row0 + 8)) * DIMC + d) >> 1] =
            packh2(oc[ni][2] * i1, oc[ni][3] * i1);
    }
}

// ============================================================================
// launch
// ============================================================================
extern "C" void kernel_launch(void* const* d_in, const int* in_sizes, int n_in,
                              void* d_out, int out_size)
{
    const float* x    = (const float*)d_in[0];
    const float* freq = (const float*)d_in[1];
    const float* Wqkv = (const float*)d_in[2];
    const float* qg   = (const float*)d_in[3];
    const float* qb   = (const float*)d_in[4];
    const float* kg   = (const float*)d_in[5];
    const float* kb   = (const float*)d_in[6];
    const float* Wp   = (const float*)d_in[7];
    const float* bp   = (const float*)d_in[8];
    float* out = (float*)d_out;

    float *qkv_p = nullptr;
    __half *xh_p = nullptr, *wqkvh_p = nullptr, *wph_p = nullptr, *attnh_p = nullptr;
    cudaGetSymbolAddress((void**)&qkv_p,   g_qkv);
    cudaGetSymbolAddress((void**)&xh_p,    g_xh);
    cudaGetSymbolAddress((void**)&wqkvh_p, g_wqkvh);
    cudaGetSymbolAddress((void**)&wph_p,   g_wph);
    cudaGetSymbolAddress((void**)&attnh_p, g_attnh);

    // 0. fp32 -> fp16 input copies (same rn rounding the GEMM staging used)
    f2h_kernel<<<(ROWS * DIMC) / 2048, 256>>>(x,    xh_p,    ROWS * DIMC);
    f2h_kernel<<<(DIMC * QKVC) / 2048, 256>>>(Wqkv, wqkvh_p, DIMC * QKVC);
    f2h_kernel<<<(DIMC * DIMC) / 2048, 256>>>(Wp,   wph_p,   DIMC * DIMC);

    // 1. qkv = x @ Wqkv          [4096,1024] @ [1024,3072]  (fp16 async mma)
    {
        dim3 grid(QKVC / 128, ROWS / 128);
        hgemm_async_kernel<<<grid, 256>>>(xh_p, wqkvh_p, qkv_p,
                                          ROWS, QKVC, DIMC, nullptr);
    }
    // 2. LN + RoPE + scatter to [B,H,N,HD] (Q pre-scaled by 1/8)
    {
        int warps = BATCH * SEQ * HEADS;
        lnrope_kernel<<<warps / 8, 256>>>(freq, qg, qb, kg, kb);
    }
    // 3. flash attention (fp16 mma) -> g_attnh [B,N,DIM] fp16
    {
        dim3 grid(SEQ / 128, BATCH * HEADS);
        attn_mma_kernel<<<grid, 256>>>();
    }
    // 4. out = attn @ Wproj + bproj   [4096,1024] @ [1024,1024]  (fp16 async mma)
    {
        dim3 grid(DIMC / 128, ROWS / 128);
        hgemm_async_kernel<<<grid, 256>>>(attnh_p, wph_p, out,
                                          ROWS, DIMC, DIMC, bp);
    }
}